// round 1
// baseline (speedup 1.0000x reference)
#include <cuda_runtime.h>
#include <cstdint>

// LightGCNConv: out = mean(X, h1, h2, h3), h_{k+1} = scatter_add(h_k[src]*ew -> dst)
// N = 100000 nodes, E = 1600000 edges, D = 64 features.

#define N_NODES 100000
#define D_FEAT  64

// Ping-pong scratch (static device memory — no allocation allowed).
__device__ float g_bufA[(size_t)N_NODES * D_FEAT];
__device__ float g_bufB[(size_t)N_NODES * D_FEAT];

// out = 0.25 * X ; bufA = 0      (n4 = N*D/4 float4 elements)
__global__ void init_kernel(const float* __restrict__ X,
                            float* __restrict__ out,
                            float* __restrict__ zbuf,
                            int n4) {
    int i = blockIdx.x * blockDim.x + threadIdx.x;
    if (i >= n4) return;
    float4 x = reinterpret_cast<const float4*>(X)[i];
    float4 o;
    o.x = 0.25f * x.x; o.y = 0.25f * x.y; o.z = 0.25f * x.z; o.w = 0.25f * x.w;
    reinterpret_cast<float4*>(out)[i] = o;
    reinterpret_cast<float4*>(zbuf)[i] = make_float4(0.f, 0.f, 0.f, 0.f);
}

// out += 0.25 * buf ; optionally zero the next scratch buffer (fused).
__global__ void accum_kernel(const float* __restrict__ buf,
                             float* __restrict__ out,
                             float* __restrict__ zbuf,   // may be null
                             int n4) {
    int i = blockIdx.x * blockDim.x + threadIdx.x;
    if (i >= n4) return;
    float4 b = reinterpret_cast<const float4*>(buf)[i];
    float4 o = reinterpret_cast<float4*>(out)[i];
    o.x += 0.25f * b.x; o.y += 0.25f * b.y; o.z += 0.25f * b.z; o.w += 0.25f * b.w;
    reinterpret_cast<float4*>(out)[i] = o;
    if (zbuf) reinterpret_cast<float4*>(zbuf)[i] = make_float4(0.f, 0.f, 0.f, 0.f);
}

// Edge-parallel SpMM: 16 threads per edge, each handles one float4 (4 feats).
// Xout[dst] += Xin[src] * ew  via vectorized global reduction (red.global.add.v4.f32).
__global__ void spmm_kernel(const float* __restrict__ Xin,
                            const int*   __restrict__ src,
                            const int*   __restrict__ dst,
                            const float* __restrict__ ew,
                            float* __restrict__ Xout,
                            int nE) {
    int tid = blockIdx.x * blockDim.x + threadIdx.x;
    int e = tid >> 4;          // edge index
    int c = tid & 15;          // float4 chunk within the 64-wide feature row
    if (e >= nE) return;

    int   s = __ldg(&src[e]);
    int   d = __ldg(&dst[e]);
    float w = __ldg(&ew[e]);

    const float4* row = reinterpret_cast<const float4*>(Xin + (size_t)s * D_FEAT);
    float4 v = __ldg(&row[c]);
    float4 m;
    m.x = v.x * w; m.y = v.y * w; m.z = v.z * w; m.w = v.w * w;

    float* p = Xout + (size_t)d * D_FEAT + (c << 2);
    asm volatile("red.global.add.v4.f32 [%0], {%1, %2, %3, %4};"
                 :: "l"(p), "f"(m.x), "f"(m.y), "f"(m.z), "f"(m.w)
                 : "memory");
}

extern "C" void kernel_launch(void* const* d_in, const int* in_sizes, int n_in,
                              void* d_out, int out_size) {
    const float* X   = (const float*)d_in[0];
    const int*   src = (const int*)  d_in[1];
    const int*   dst = (const int*)  d_in[2];
    const float* ew  = (const float*)d_in[3];
    float* out = (float*)d_out;

    const int nE = in_sizes[1];
    const int n4 = in_sizes[0] / 4;      // float4 count of the node-feature tensor

    float* bufA = nullptr;
    float* bufB = nullptr;
    cudaGetSymbolAddress((void**)&bufA, g_bufA);
    cudaGetSymbolAddress((void**)&bufB, g_bufB);

    const int TB = 256;
    const int gridN = (n4 + TB - 1) / TB;
    const int spmmThreads = nE * 16;
    const int gridE = (spmmThreads + TB - 1) / TB;

    // out = 0.25*X ; bufA = 0
    init_kernel<<<gridN, TB>>>(X, out, bufA, n4);
    // h1 -> bufA
    spmm_kernel<<<gridE, TB>>>(X, src, dst, ew, bufA, nE);
    // out += 0.25*h1 ; bufB = 0
    accum_kernel<<<gridN, TB>>>(bufA, out, bufB, n4);
    // h2 -> bufB
    spmm_kernel<<<gridE, TB>>>(bufA, src, dst, ew, bufB, nE);
    // out += 0.25*h2 ; bufA = 0
    accum_kernel<<<gridN, TB>>>(bufB, out, bufA, n4);
    // h3 -> bufA
    spmm_kernel<<<gridE, TB>>>(bufB, src, dst, ew, bufA, nE);
    // out += 0.25*h3
    accum_kernel<<<gridN, TB>>>(bufA, out, nullptr, n4);
}

// round 2
// speedup vs baseline: 1.9186x; 1.9186x over previous
#include <cuda_runtime.h>
#include <cstdint>

// LightGCN: out = 0.25*(X + h1 + h2 + h3), h_{k+1} = A h_k (weighted scatter-sum)
// Pull-based formulation: build dst-sorted CSR once per launch, then 3 gather-
// and-reduce layers with NO atomics on the feature data.

#define N_NODES 100000
#define D_FEAT  64
#define MAX_E   1600000
#define SCAN_BS 1024
#define N_SCAN_BLOCKS ((N_NODES + SCAN_BS - 1) / SCAN_BS)   // 98

// Static scratch (no allocation allowed).
__device__ float g_bufA[(size_t)N_NODES * D_FEAT];
__device__ float g_bufB[(size_t)N_NODES * D_FEAT];
__device__ int   g_deg[N_NODES];
__device__ int   g_incl[N_NODES];
__device__ int   g_blockSums[N_SCAN_BLOCKS];
__device__ int   g_blockOff[N_SCAN_BLOCKS];
__device__ int   g_off[N_NODES + 1];
__device__ int   g_cursor[N_NODES];
__device__ int   g_ssrc[MAX_E];
__device__ float g_sew[MAX_E];

// ---------------- CSR construction ----------------

__global__ void k_zero_deg(int n) {
    int i = blockIdx.x * blockDim.x + threadIdx.x;
    if (i < n) g_deg[i] = 0;
}

__global__ void k_hist(const int* __restrict__ dst, int nE) {
    int e = blockIdx.x * blockDim.x + threadIdx.x;
    if (e < nE) atomicAdd(&g_deg[dst[e]], 1);
}

// Per-block inclusive scan (Hillis-Steele) + block sums.
__global__ void k_scan_block(int n) {
    __shared__ int sh[SCAN_BS];
    int t = threadIdx.x;
    int i = blockIdx.x * SCAN_BS + t;
    int v = (i < n) ? g_deg[i] : 0;
    sh[t] = v;
    __syncthreads();
    for (int d = 1; d < SCAN_BS; d <<= 1) {
        int x = (t >= d) ? sh[t - d] : 0;
        __syncthreads();
        sh[t] += x;
        __syncthreads();
    }
    if (i < n) g_incl[i] = sh[t];
    if (t == SCAN_BS - 1) g_blockSums[blockIdx.x] = sh[t];
}

// Tiny exclusive scan of the 98 block sums (single thread — trivial size).
__global__ void k_scan_tops(int nb) {
    if (threadIdx.x == 0 && blockIdx.x == 0) {
        int run = 0;
        for (int b = 0; b < nb; b++) {
            g_blockOff[b] = run;
            run += g_blockSums[b];
        }
    }
}

__global__ void k_finalize_off(int n, int nE) {
    int i = blockIdx.x * blockDim.x + threadIdx.x;
    if (i >= n) return;
    int excl = g_incl[i] + g_blockOff[i >> 10] - g_deg[i];
    g_off[i] = excl;
    g_cursor[i] = excl;
    if (i == n - 1) g_off[n] = nE;
}

__global__ void k_scatter(const int* __restrict__ src,
                          const int* __restrict__ dst,
                          const float* __restrict__ ew, int nE) {
    int e = blockIdx.x * blockDim.x + threadIdx.x;
    if (e >= nE) return;
    int d = dst[e];
    int pos = atomicAdd(&g_cursor[d], 1);
    g_ssrc[pos] = src[e];
    g_sew[pos]  = ew[e];
}

// ---------------- Pull SpMM ----------------
// One warp per dst node. Lanes 0-15 process even edges, lanes 16-31 odd edges
// (doubles MLP). Each lane owns one float4 column chunk (16 x 16B = 256B row).

__device__ __forceinline__ float4 warp_node_reduce(const float* __restrict__ Xin,
                                                   int node, int c, int half) {
    int begin = g_off[node], end = g_off[node + 1];
    float4 acc = make_float4(0.f, 0.f, 0.f, 0.f);
    for (int e = begin + half; e < end; e += 2) {
        int   s = g_ssrc[e];
        float w = g_sew[e];
        float4 v = *reinterpret_cast<const float4*>(Xin + (size_t)s * D_FEAT + (c << 2));
        acc.x += w * v.x; acc.y += w * v.y; acc.z += w * v.z; acc.w += w * v.w;
    }
    // combine the two edge-halves (same columns in both halves)
    acc.x += __shfl_xor_sync(0xffffffff, acc.x, 16);
    acc.y += __shfl_xor_sync(0xffffffff, acc.y, 16);
    acc.z += __shfl_xor_sync(0xffffffff, acc.z, 16);
    acc.w += __shfl_xor_sync(0xffffffff, acc.w, 16);
    return acc;
}

__global__ void k_pull(const float* __restrict__ Xin,
                       float* __restrict__ Xout) {
    int gwarp = (blockIdx.x * blockDim.x + threadIdx.x) >> 5;
    if (gwarp >= N_NODES) return;
    int lane = threadIdx.x & 31;
    int half = lane >> 4;
    int c    = lane & 15;
    float4 acc = warp_node_reduce(Xin, gwarp, c, half);
    if (half == 0)
        *reinterpret_cast<float4*>(Xout + (size_t)gwarp * D_FEAT + (c << 2)) = acc;
}

// Final layer fused with the mean: out = 0.25*(X + h1 + h2 + h3)
__global__ void k_pull_final(const float* __restrict__ Xin,   // h2
                             const float* __restrict__ X,
                             const float* __restrict__ h1,
                             float* __restrict__ out) {
    int gwarp = (blockIdx.x * blockDim.x + threadIdx.x) >> 5;
    if (gwarp >= N_NODES) return;
    int lane = threadIdx.x & 31;
    int half = lane >> 4;
    int c    = lane & 15;
    float4 acc = warp_node_reduce(Xin, gwarp, c, half);   // h3 chunk
    if (half == 0) {
        size_t idx = (size_t)gwarp * D_FEAT + (c << 2);
        float4 x0 = *reinterpret_cast<const float4*>(X   + idx);
        float4 x1 = *reinterpret_cast<const float4*>(h1  + idx);
        float4 x2 = *reinterpret_cast<const float4*>(Xin + idx);
        float4 o;
        o.x = 0.25f * (x0.x + x1.x + x2.x + acc.x);
        o.y = 0.25f * (x0.y + x1.y + x2.y + acc.y);
        o.z = 0.25f * (x0.z + x1.z + x2.z + acc.z);
        o.w = 0.25f * (x0.w + x1.w + x2.w + acc.w);
        *reinterpret_cast<float4*>(out + idx) = o;
    }
}

extern "C" void kernel_launch(void* const* d_in, const int* in_sizes, int n_in,
                              void* d_out, int out_size) {
    const float* X   = (const float*)d_in[0];
    const int*   src = (const int*)  d_in[1];
    const int*   dst = (const int*)  d_in[2];
    const float* ew  = (const float*)d_in[3];
    float* out = (float*)d_out;

    const int nE = in_sizes[1];

    float* bufA = nullptr;
    float* bufB = nullptr;
    cudaGetSymbolAddress((void**)&bufA, g_bufA);
    cudaGetSymbolAddress((void**)&bufB, g_bufB);

    const int TB = 256;
    const int gridNode = (N_NODES + TB - 1) / TB;
    const int gridE    = (nE + TB - 1) / TB;
    const int gridPull = (N_NODES * 32 + TB - 1) / TB;   // warp per node

    // --- build dst-sorted CSR ---
    k_zero_deg<<<gridNode, TB>>>(N_NODES);
    k_hist<<<gridE, TB>>>(dst, nE);
    k_scan_block<<<N_SCAN_BLOCKS, SCAN_BS>>>(N_NODES);
    k_scan_tops<<<1, 32>>>(N_SCAN_BLOCKS);
    k_finalize_off<<<gridNode, TB>>>(N_NODES, nE);
    k_scatter<<<gridE, TB>>>(src, dst, ew, nE);

    // --- 3 pull layers, final fused with the mean ---
    k_pull<<<gridPull, TB>>>(X, bufA);                    // h1
    k_pull<<<gridPull, TB>>>(bufA, bufB);                 // h2
    k_pull_final<<<gridPull, TB>>>(bufB, X, bufA, out);   // h3 + mean
}